// round 9
// baseline (speedup 1.0000x reference)
#include <cuda_runtime.h>
#include <cuda_fp16.h>
#include <cstdint>

#define BSZ 32
#define CDIM 512
#define TDIM 1024
#define SCALE_F 0.04419417382415922f  // 1/sqrt(512)
#define CT (CDIM * TDIM)
#define CC (CDIM * CDIM)

// ---------------------------------------------------------------------------
// Scratch (allocation-free rule: __device__ globals)
// ---------------------------------------------------------------------------
__device__ __align__(16) __half g_w[3 * CC];                 // fp16 W [m][d][c]
__device__ __align__(16) __half g_x[(size_t)BSZ * CT];       // fp16 x [b][c][t]
__device__ __align__(16) __half g_q[(size_t)BSZ * CT];       // fp16 q [b][c][t]
__device__ __align__(16) __half g_k[(size_t)BSZ * CT];       // fp16 k [b][d][t]
__device__ __align__(16) __half g_v[(size_t)BSZ * CT];       // fp16 v [b][d][t]
__device__ __align__(16) __half g_a[(size_t)BSZ * CC];       // fp16 attn [b][c][d]
__device__ __align__(16) float  g_e[(size_t)BSZ * CC];       // energy fp32 [b][c][d]

// SMEM strides (fp16 elems): rows shift 16B mod 128B -> conflict-free ldmatrix.
#define ASTR 72
#define BSTR 136

// ---------------------------------------------------------------------------
// PTX wrappers
// ---------------------------------------------------------------------------
__device__ __forceinline__ void ldsm4(uint32_t& r0, uint32_t& r1, uint32_t& r2, uint32_t& r3,
                                      const void* p) {
    uint32_t a = (uint32_t)__cvta_generic_to_shared(p);
    asm volatile("ldmatrix.sync.aligned.m8n8.x4.shared.b16 {%0,%1,%2,%3},[%4];"
                 : "=r"(r0), "=r"(r1), "=r"(r2), "=r"(r3) : "r"(a));
}
__device__ __forceinline__ void ldsm4t(uint32_t& r0, uint32_t& r1, uint32_t& r2, uint32_t& r3,
                                       const void* p) {
    uint32_t a = (uint32_t)__cvta_generic_to_shared(p);
    asm volatile("ldmatrix.sync.aligned.m8n8.x4.trans.shared.b16 {%0,%1,%2,%3},[%4];"
                 : "=r"(r0), "=r"(r1), "=r"(r2), "=r"(r3) : "r"(a));
}
__device__ __forceinline__ void mma_f16(float* d, const uint32_t* a, const uint32_t* b) {
    asm volatile(
        "mma.sync.aligned.m16n8k16.row.col.f32.f16.f16.f32 "
        "{%0,%1,%2,%3},{%4,%5,%6,%7},{%8,%9},{%0,%1,%2,%3};"
        : "+f"(d[0]), "+f"(d[1]), "+f"(d[2]), "+f"(d[3])
        : "r"(a[0]), "r"(a[1]), "r"(a[2]), "r"(a[3]), "r"(b[0]), "r"(b[1]));
}
__device__ __forceinline__ void cpa16(uint32_t dst, const void* src) {
    asm volatile("cp.async.cg.shared.global [%0], [%1], 16;" :: "r"(dst), "l"(src));
}
__device__ __forceinline__ void cpcommit() { asm volatile("cp.async.commit_group;"); }
__device__ __forceinline__ void cpwait1()  { asm volatile("cp.async.wait_group 1;"); }

// ---------------------------------------------------------------------------
// Core: CTA tile 128x128, BK=64, 128 threads = 4 warps (2m x 2n),
// warp tile 64x64, fp16 single-pass, 2-stage cp.async double buffer.
// A [M,K] k-contig. BNT=false: B [K,N] n-contig. BNT=true: B [N,K] k-contig.
// ---------------------------------------------------------------------------
template <bool BNT>
__device__ __forceinline__ void mm_core(
    const __half* __restrict__ A, int lda,
    const __half* __restrict__ B, int ldb,
    int K, char* sm, float acc[4][8][4])
{
    constexpr int AP = 128 * ASTR * 2;                     // 18432
    constexpr int BP = BNT ? 128 * ASTR * 2 : 64 * BSTR * 2;
    constexpr int SB = AP + BP;

    const int tid  = threadIdx.x;
    const int lane = tid & 31;
    const int wid  = tid >> 5;
    const int wm   = wid & 1;    // m offset wm*64
    const int wn   = wid >> 1;   // n offset wn*64
    const uint32_t s0 = (uint32_t)__cvta_generic_to_shared(sm);

#pragma unroll
    for (int mi = 0; mi < 4; mi++)
#pragma unroll
        for (int ni = 0; ni < 8; ni++)
#pragma unroll
            for (int r = 0; r < 4; r++) acc[mi][ni][r] = 0.0f;

    auto stage = [&](int buf, int kt) {
        uint32_t sb = s0 + buf * SB;
        {   // A: 128 rows x 64 k, one full row (128B) per thread
            int row = tid;
            uint32_t d = sb + row * (ASTR * 2);
            const __half* s = A + (size_t)row * lda + kt;
#pragma unroll
            for (int j = 0; j < 8; j++) cpa16(d + j * 16, s + j * 8);
        }
        if (BNT) {  // B: 128 n-rows x 64 k
            int row = tid;
            uint32_t d = sb + AP + row * (ASTR * 2);
            const __half* s = B + (size_t)row * ldb + kt;
#pragma unroll
            for (int j = 0; j < 8; j++) cpa16(d + j * 16, s + j * 8);
        } else {    // B: 64 k-rows x 128 n, half row (128B) per thread
            int row = tid >> 1;
            int e0  = (tid & 1) * 64;
            uint32_t d = sb + AP + (row * BSTR + e0) * 2;
            const __half* s = B + (size_t)(kt + row) * ldb + e0;
#pragma unroll
            for (int j = 0; j < 8; j++) cpa16(d + j * 16, s + j * 8);
        }
    };

    stage(0, 0);
    cpcommit();
    const int NT = K / 64;
    for (int it = 0; it < NT; ++it) {
        if (it + 1 < NT) stage((it + 1) & 1, (it + 1) * 64);
        cpcommit();
        cpwait1();
        __syncthreads();
        char* buf = sm + (it & 1) * SB;
        const __half* sA = (const __half*)buf;
        const __half* sB = (const __half*)(buf + AP);

#pragma unroll
        for (int ks = 0; ks < 4; ++ks) {
            uint32_t ah[4][4];
#pragma unroll
            for (int mi = 0; mi < 4; mi++) {
                int arow = wm * 64 + mi * 16 + (lane & 15);
                int acol = ks * 16 + (lane >> 4) * 8;
                ldsm4(ah[mi][0], ah[mi][1], ah[mi][2], ah[mi][3], &sA[arow * ASTR + acol]);
            }
            uint32_t bh[4][4];
#pragma unroll
            for (int p = 0; p < 4; p++) {
                if (!BNT) {
                    int brow = ks * 16 + (lane & 15);
                    int bcol = wn * 64 + p * 16 + (lane >> 4) * 8;
                    ldsm4t(bh[p][0], bh[p][1], bh[p][2], bh[p][3], &sB[brow * BSTR + bcol]);
                } else {
                    int q    = lane >> 3;
                    int nrow = wn * 64 + p * 16 + (lane & 7) + ((q & 2) ? 8 : 0);
                    int kcol = ks * 16 + ((q & 1) ? 8 : 0);
                    ldsm4(bh[p][0], bh[p][1], bh[p][2], bh[p][3], &sB[nrow * ASTR + kcol]);
                }
            }
#pragma unroll
            for (int mi = 0; mi < 4; mi++)
#pragma unroll
                for (int p = 0; p < 4; p++)
#pragma unroll
                    for (int t = 0; t < 2; t++)
                        mma_f16(acc[mi][p * 2 + t], ah[mi], &bh[p][t * 2]);
        }
        __syncthreads();
    }
}

#define SMEM_NN (2 * (128 * ASTR * 2 + 64 * BSTR * 2))    // 71680
#define SMEM_NT (2 * (128 * ASTR * 2 + 128 * ASTR * 2))   // 73728

// ---------------------------------------------------------------------------
// Prep kernels: fp16 casts
// ---------------------------------------------------------------------------
__global__ __launch_bounds__(256) void wprep(
    const float* __restrict__ Wq, const float* __restrict__ Wk, const float* __restrict__ Wv)
{
    const int m = blockIdx.y;
    const float* W = (m == 0) ? Wq : ((m == 1) ? Wk : Wv);
    size_t i = ((size_t)blockIdx.x * 256 + threadIdx.x) * 8;
    float4 a = *reinterpret_cast<const float4*>(W + i);
    float4 b = *reinterpret_cast<const float4*>(W + i + 4);
    union { __half h[8]; uint4 u; } o;
    o.h[0] = __float2half(a.x); o.h[1] = __float2half(a.y);
    o.h[2] = __float2half(a.z); o.h[3] = __float2half(a.w);
    o.h[4] = __float2half(b.x); o.h[5] = __float2half(b.y);
    o.h[6] = __float2half(b.z); o.h[7] = __float2half(b.w);
    *reinterpret_cast<uint4*>(&g_w[(size_t)m * CC + i]) = o.u;
}

__global__ __launch_bounds__(256) void xprep(const float* __restrict__ x)
{
    size_t i = ((size_t)blockIdx.x * 256 + threadIdx.x) * 8;
    float4 a = *reinterpret_cast<const float4*>(x + i);
    float4 b = *reinterpret_cast<const float4*>(x + i + 4);
    union { __half h[8]; uint4 u; } o;
    o.h[0] = __float2half(a.x); o.h[1] = __float2half(a.y);
    o.h[2] = __float2half(a.z); o.h[3] = __float2half(a.w);
    o.h[4] = __float2half(b.x); o.h[5] = __float2half(b.y);
    o.h[6] = __float2half(b.z); o.h[7] = __float2half(b.w);
    *reinterpret_cast<uint4*>(&g_x[i]) = o.u;
}

// ---------------------------------------------------------------------------
// 1) q/k/v projection: out[ch,t] = fp16(gate * (W @ x + bias))
//    grid (8, 4, 96), z = m*32 + b
// ---------------------------------------------------------------------------
__global__ __launch_bounds__(128) void qkv_mm(
    const float* __restrict__ gq, const float* __restrict__ gk, const float* __restrict__ gv,
    const float* __restrict__ bq, const float* __restrict__ bk, const float* __restrict__ bv)
{
    extern __shared__ char dsm[];
    const int z = blockIdx.z;
    const int b = z & 31;
    const int m = z >> 5;
    const float* gate = (m == 0) ? gq : ((m == 1) ? gk : gv);
    const float* bias = (m == 0) ? bq : ((m == 1) ? bk : bv);
    __half* outp      = (m == 0) ? g_q : ((m == 1) ? g_k : g_v);

    const int m0 = blockIdx.y * 128;  // d
    const int n0 = blockIdx.x * 128;  // t
    const size_t base = (size_t)b * CT;

    float acc[4][8][4];
    mm_core<false>(g_w + (size_t)m * CC + (size_t)m0 * CDIM, CDIM,
                   g_x + base + n0, TDIM, CDIM, dsm, acc);

    const int lane = threadIdx.x & 31;
    const int wid  = threadIdx.x >> 5;
    const int wm = wid & 1, wn = wid >> 1;
#pragma unroll
    for (int mi = 0; mi < 4; mi++)
#pragma unroll
        for (int ni = 0; ni < 8; ni++) {
            int r = m0 + wm * 64 + mi * 16 + (lane >> 2);
            int c = n0 + wn * 64 + ni * 8 + (lane & 3) * 2;
#pragma unroll
            for (int h = 0; h < 2; h++) {
                int d = r + h * 8;
                float bi = bias[d];
                size_t off = base + (size_t)d * TDIM + c;
                float2 g = *reinterpret_cast<const float2*>(gate + off);
                *reinterpret_cast<__half2*>(outp + off) =
                    __floats2half2_rn((acc[mi][ni][h * 2 + 0] + bi) * g.x,
                                      (acc[mi][ni][h * 2 + 1] + bi) * g.y);
            }
        }
}

// ---------------------------------------------------------------------------
// 2) energy: E[c,d] = SCALE * sum_t q[c,t] k[d,t]   grid (4, 4, 32)
// ---------------------------------------------------------------------------
__global__ __launch_bounds__(128) void energy_mm()
{
    extern __shared__ char dsm[];
    const int b  = blockIdx.z;
    const int m0 = blockIdx.y * 128;  // c
    const int n0 = blockIdx.x * 128;  // d
    const size_t base = (size_t)b * CT;

    float acc[4][8][4];
    mm_core<true>(g_q + base + (size_t)m0 * TDIM, TDIM,
                  g_k + base + (size_t)n0 * TDIM, TDIM, TDIM, dsm, acc);

    const int lane = threadIdx.x & 31;
    const int wid  = threadIdx.x >> 5;
    const int wm = wid & 1, wn = wid >> 1;
    const size_t ebase = (size_t)b * CC;
#pragma unroll
    for (int mi = 0; mi < 4; mi++)
#pragma unroll
        for (int ni = 0; ni < 8; ni++) {
            int r = m0 + wm * 64 + mi * 16 + (lane >> 2);
            int c = n0 + wn * 64 + ni * 8 + (lane & 3) * 2;
#pragma unroll
            for (int h = 0; h < 2; h++) {
                size_t off = ebase + (size_t)(r + h * 8) * CDIM + c;
                *reinterpret_cast<float2*>(g_e + off) =
                    make_float2(acc[mi][ni][h * 2 + 0] * SCALE_F,
                                acc[mi][ni][h * 2 + 1] * SCALE_F);
            }
        }
}

// ---------------------------------------------------------------------------
// 3) softmax over d (512) -> fp16 attn.  grid 16384 x 256
// ---------------------------------------------------------------------------
__global__ __launch_bounds__(256) void softmax_kernel()
{
    const size_t row = blockIdx.x;
    const float* e = g_e + row * CDIM;
    const int tid  = threadIdx.x;
    const int lane = tid & 31;
    const int warp = tid >> 5;

    __shared__ float wmax[8], wsum[8];

    float v0 = e[tid];
    float v1 = e[tid + 256];
    float m = fmaxf(v0, v1);
#pragma unroll
    for (int o = 16; o > 0; o >>= 1) m = fmaxf(m, __shfl_xor_sync(0xFFFFFFFFu, m, o));
    if (lane == 0) wmax[warp] = m;
    __syncthreads();
    float bm = wmax[0];
#pragma unroll
    for (int w = 1; w < 8; w++) bm = fmaxf(bm, wmax[w]);

    float e0 = __expf(v0 - bm);
    float e1 = __expf(v1 - bm);
    float s = e0 + e1;
#pragma unroll
    for (int o = 16; o > 0; o >>= 1) s += __shfl_xor_sync(0xFFFFFFFFu, s, o);
    if (lane == 0) wsum[warp] = s;
    __syncthreads();
    float bs = 0.0f;
#pragma unroll
    for (int w = 0; w < 8; w++) bs += wsum[w];

    const float inv = 1.0f / bs;
    g_a[row * CDIM + tid]       = __float2half(e0 * inv);
    g_a[row * CDIM + tid + 256] = __float2half(e1 * inv);
}

// ---------------------------------------------------------------------------
// 4) out[c,t] = sum_d attn[c,d] v[d,t]   grid (8, 4, 32)
// ---------------------------------------------------------------------------
__global__ __launch_bounds__(128) void out_mm(float* __restrict__ out)
{
    extern __shared__ char dsm[];
    const int b  = blockIdx.z;
    const int m0 = blockIdx.y * 128;  // c
    const int n0 = blockIdx.x * 128;  // t
    const size_t base  = (size_t)b * CT;
    const size_t ebase = (size_t)b * CC;

    float acc[4][8][4];
    mm_core<false>(g_a + ebase + (size_t)m0 * CDIM, CDIM,
                   g_v + base + n0, TDIM, CDIM, dsm, acc);

    const int lane = threadIdx.x & 31;
    const int wid  = threadIdx.x >> 5;
    const int wm = wid & 1, wn = wid >> 1;
#pragma unroll
    for (int mi = 0; mi < 4; mi++)
#pragma unroll
        for (int ni = 0; ni < 8; ni++) {
            int r = m0 + wm * 64 + mi * 16 + (lane >> 2);
            int c = n0 + wn * 64 + ni * 8 + (lane & 3) * 2;
#pragma unroll
            for (int h = 0; h < 2; h++) {
                size_t off = base + (size_t)(r + h * 8) * TDIM + c;
                *reinterpret_cast<float2*>(out + off) =
                    make_float2(acc[mi][ni][h * 2 + 0], acc[mi][ni][h * 2 + 1]);
            }
        }
}

// ---------------------------------------------------------------------------
extern "C" void kernel_launch(void* const* d_in, const int* in_sizes, int n_in,
                              void* d_out, int out_size)
{
    const float* x  = (const float*)d_in[0];
    const float* gq = (const float*)d_in[1];
    const float* gk = (const float*)d_in[2];
    const float* gv = (const float*)d_in[3];
    const float* Wq = (const float*)d_in[4];
    const float* bq = (const float*)d_in[5];
    const float* Wk = (const float*)d_in[6];
    const float* bk = (const float*)d_in[7];
    const float* Wv = (const float*)d_in[8];
    const float* bv = (const float*)d_in[9];
    float* out = (float*)d_out;

    cudaFuncSetAttribute(qkv_mm,    cudaFuncAttributeMaxDynamicSharedMemorySize, SMEM_NN);
    cudaFuncSetAttribute(energy_mm, cudaFuncAttributeMaxDynamicSharedMemorySize, SMEM_NT);
    cudaFuncSetAttribute(out_mm,    cudaFuncAttributeMaxDynamicSharedMemorySize, SMEM_NN);

    wprep<<<dim3(CC / 2048, 3), 256>>>(Wq, Wk, Wv);
    xprep<<<(unsigned)(((size_t)BSZ * CT) / 2048), 256>>>(x);

    qkv_mm<<<dim3(TDIM / 128, CDIM / 128, 3 * BSZ), 128, SMEM_NN>>>(gq, gk, gv, bq, bk, bv);

    energy_mm<<<dim3(CDIM / 128, CDIM / 128, BSZ), 128, SMEM_NT>>>();

    softmax_kernel<<<BSZ * CDIM, 256>>>();

    out_mm<<<dim3(TDIM / 128, CDIM / 128, BSZ), 128, SMEM_NN>>>(out);
}

// round 12
// speedup vs baseline: 1.7136x; 1.7136x over previous
#include <cuda_runtime.h>
#include <cuda_fp16.h>
#include <cstdint>

#define BSZ 32
#define CDIM 512
#define TDIM 1024
#define SCALE_F 0.04419417382415922f  // 1/sqrt(512)
#define CT (CDIM * TDIM)
#define CC (CDIM * CDIM)

// ---------------------------------------------------------------------------
// Scratch (allocation-free rule: __device__ globals)
// ---------------------------------------------------------------------------
__device__ __align__(16) __half g_w[3 * CC];                 // fp16 W [m][d][c]
__device__ __align__(16) __half g_x[(size_t)BSZ * CT];       // fp16 x [b][c][t]
__device__ __align__(16) __half g_q[(size_t)BSZ * CT];       // fp16 q [b][c][t]
__device__ __align__(16) __half g_k[(size_t)BSZ * CT];       // fp16 k [b][d][t]
__device__ __align__(16) __half g_v[(size_t)BSZ * CT];       // fp16 v [b][d][t]
__device__ __align__(16) __half g_a[(size_t)BSZ * CC];       // fp16 attn [b][c][d]
__device__ __align__(16) float  g_e[(size_t)BSZ * CC];       // energy fp32 [b][c][d]

// SMEM strides (fp16 elems): rows shift 16B mod 128B -> conflict-free ldmatrix.
#define ASTR 72
#define BSTR 136

// ---------------------------------------------------------------------------
// PTX wrappers
// ---------------------------------------------------------------------------
__device__ __forceinline__ void ldsm4(uint32_t& r0, uint32_t& r1, uint32_t& r2, uint32_t& r3,
                                      const void* p) {
    uint32_t a = (uint32_t)__cvta_generic_to_shared(p);
    asm volatile("ldmatrix.sync.aligned.m8n8.x4.shared.b16 {%0,%1,%2,%3},[%4];"
                 : "=r"(r0), "=r"(r1), "=r"(r2), "=r"(r3) : "r"(a));
}
__device__ __forceinline__ void ldsm4t(uint32_t& r0, uint32_t& r1, uint32_t& r2, uint32_t& r3,
                                       const void* p) {
    uint32_t a = (uint32_t)__cvta_generic_to_shared(p);
    asm volatile("ldmatrix.sync.aligned.m8n8.x4.trans.shared.b16 {%0,%1,%2,%3},[%4];"
                 : "=r"(r0), "=r"(r1), "=r"(r2), "=r"(r3) : "r"(a));
}
__device__ __forceinline__ void mma_f16(float* d, const uint32_t* a, const uint32_t* b) {
    asm volatile(
        "mma.sync.aligned.m16n8k16.row.col.f32.f16.f16.f32 "
        "{%0,%1,%2,%3},{%4,%5,%6,%7},{%8,%9},{%0,%1,%2,%3};"
        : "+f"(d[0]), "+f"(d[1]), "+f"(d[2]), "+f"(d[3])
        : "r"(a[0]), "r"(a[1]), "r"(a[2]), "r"(a[3]), "r"(b[0]), "r"(b[1]));
}
__device__ __forceinline__ void cpa16(uint32_t dst, const void* src) {
    asm volatile("cp.async.cg.shared.global [%0], [%1], 16;" :: "r"(dst), "l"(src));
}
__device__ __forceinline__ void cpcommit() { asm volatile("cp.async.commit_group;"); }
__device__ __forceinline__ void cpwait1()  { asm volatile("cp.async.wait_group 1;"); }

// ---------------------------------------------------------------------------
// Core: CTA tile 128x128, BK=64, 256 threads = 8 warps (4m x 2n), warp 32x64,
// fp16 single-pass, 2-stage cp.async smem double buffer +
// register-level fragment double buffer (ldsm for ks+1 overlaps MMAs of ks).
// A [M,K] k-contig. BNT=false: B [K,N] n-contig. BNT=true: B [N,K] k-contig.
// ---------------------------------------------------------------------------
template <bool BNT>
__device__ __forceinline__ void mm_core(
    const __half* __restrict__ A, int lda,
    const __half* __restrict__ B, int ldb,
    int K, char* sm, float acc[2][8][4])
{
    constexpr int AP = 128 * ASTR * 2;                     // 18432
    constexpr int BP = BNT ? 128 * ASTR * 2 : 64 * BSTR * 2;
    constexpr int SB = AP + BP;

    const int tid  = threadIdx.x;
    const int lane = tid & 31;
    const int wid  = tid >> 5;
    const int wm   = wid & 3;    // m offset wm*32
    const int wn   = wid >> 2;   // n offset wn*64
    const uint32_t s0 = (uint32_t)__cvta_generic_to_shared(sm);

#pragma unroll
    for (int mi = 0; mi < 2; mi++)
#pragma unroll
        for (int ni = 0; ni < 8; ni++)
#pragma unroll
            for (int r = 0; r < 4; r++) acc[mi][ni][r] = 0.0f;

    auto stage = [&](int buf, int kt) {
        uint32_t sb = s0 + buf * SB;
        {   // A: 128 rows x 64 k
            int row = tid >> 1;
            int e0  = (tid & 1) * 32;
            uint32_t d = sb + (row * ASTR + e0) * 2;
            const __half* s = A + (size_t)row * lda + kt + e0;
#pragma unroll
            for (int j = 0; j < 4; j++) cpa16(d + j * 16, s + j * 8);
        }
        if (BNT) {  // B: 128 n-rows x 64 k
            int row = tid >> 1;
            int e0  = (tid & 1) * 32;
            uint32_t d = sb + AP + (row * ASTR + e0) * 2;
            const __half* s = B + (size_t)row * ldb + kt + e0;
#pragma unroll
            for (int j = 0; j < 4; j++) cpa16(d + j * 16, s + j * 8);
        } else {    // B: 64 k-rows x 128 n
            int row = tid >> 2;
            int e0  = (tid & 3) * 32;
            uint32_t d = sb + AP + (row * BSTR + e0) * 2;
            const __half* s = B + (size_t)(kt + row) * ldb + e0;
#pragma unroll
            for (int j = 0; j < 4; j++) cpa16(d + j * 16, s + j * 8);
        }
    };

    uint32_t ah[2][2][4];   // [pipe][mi][frag]
    uint32_t bh[2][4][4];   // [pipe][p][frag]

    auto load_frag = [&](const __half* sA, const __half* sB, int ks, int pb) {
#pragma unroll
        for (int mi = 0; mi < 2; mi++) {
            int arow = wm * 32 + mi * 16 + (lane & 15);
            int acol = ks * 16 + (lane >> 4) * 8;
            ldsm4(ah[pb][mi][0], ah[pb][mi][1], ah[pb][mi][2], ah[pb][mi][3],
                  &sA[arow * ASTR + acol]);
        }
#pragma unroll
        for (int p = 0; p < 4; p++) {
            if (!BNT) {
                int brow = ks * 16 + (lane & 15);
                int bcol = wn * 64 + p * 16 + (lane >> 4) * 8;
                ldsm4t(bh[pb][p][0], bh[pb][p][1], bh[pb][p][2], bh[pb][p][3],
                       &sB[brow * BSTR + bcol]);
            } else {
                int q    = lane >> 3;
                int nrow = wn * 64 + p * 16 + (lane & 7) + ((q & 2) ? 8 : 0);
                int kcol = ks * 16 + ((q & 1) ? 8 : 0);
                ldsm4(bh[pb][p][0], bh[pb][p][1], bh[pb][p][2], bh[pb][p][3],
                      &sB[nrow * ASTR + kcol]);
            }
        }
    };

    stage(0, 0);
    cpcommit();
    const int NT = K / 64;
    for (int it = 0; it < NT; ++it) {
        if (it + 1 < NT) stage((it + 1) & 1, (it + 1) * 64);
        cpcommit();
        cpwait1();
        __syncthreads();
        char* buf = sm + (it & 1) * SB;
        const __half* sA = (const __half*)buf;
        const __half* sB = (const __half*)(buf + AP);

        load_frag(sA, sB, 0, 0);
#pragma unroll
        for (int ks = 0; ks < 4; ++ks) {
            if (ks < 3) load_frag(sA, sB, ks + 1, (ks + 1) & 1);
            const int pb = ks & 1;
#pragma unroll
            for (int mi = 0; mi < 2; mi++)
#pragma unroll
                for (int p = 0; p < 4; p++)
#pragma unroll
                    for (int t = 0; t < 2; t++)
                        mma_f16(acc[mi][p * 2 + t], ah[pb][mi], &bh[pb][p][t * 2]);
        }
        __syncthreads();
    }
}

#define SMEM_NN (2 * (128 * ASTR * 2 + 64 * BSTR * 2))    // 71680
#define SMEM_NT (2 * (128 * ASTR * 2 + 128 * ASTR * 2))   // 73728

// ---------------------------------------------------------------------------
// Prep kernels: fp16 casts
// ---------------------------------------------------------------------------
__global__ __launch_bounds__(256) void wprep(
    const float* __restrict__ Wq, const float* __restrict__ Wk, const float* __restrict__ Wv)
{
    const int m = blockIdx.y;
    const float* W = (m == 0) ? Wq : ((m == 1) ? Wk : Wv);
    size_t i = ((size_t)blockIdx.x * 256 + threadIdx.x) * 8;
    float4 a = *reinterpret_cast<const float4*>(W + i);
    float4 b = *reinterpret_cast<const float4*>(W + i + 4);
    union { __half h[8]; uint4 u; } o;
    o.h[0] = __float2half(a.x); o.h[1] = __float2half(a.y);
    o.h[2] = __float2half(a.z); o.h[3] = __float2half(a.w);
    o.h[4] = __float2half(b.x); o.h[5] = __float2half(b.y);
    o.h[6] = __float2half(b.z); o.h[7] = __float2half(b.w);
    *reinterpret_cast<uint4*>(&g_w[(size_t)m * CC + i]) = o.u;
}

__global__ __launch_bounds__(256) void xprep(const float* __restrict__ x)
{
    size_t i = ((size_t)blockIdx.x * 256 + threadIdx.x) * 8;
    float4 a = *reinterpret_cast<const float4*>(x + i);
    float4 b = *reinterpret_cast<const float4*>(x + i + 4);
    union { __half h[8]; uint4 u; } o;
    o.h[0] = __float2half(a.x); o.h[1] = __float2half(a.y);
    o.h[2] = __float2half(a.z); o.h[3] = __float2half(a.w);
    o.h[4] = __float2half(b.x); o.h[5] = __float2half(b.y);
    o.h[6] = __float2half(b.z); o.h[7] = __float2half(b.w);
    *reinterpret_cast<uint4*>(&g_x[i]) = o.u;
}

// ---------------------------------------------------------------------------
// 1) q/k/v projection: out[ch,t] = fp16(gate * (W @ x + bias))
//    grid (8, 4, 96), z = m*32 + b
// ---------------------------------------------------------------------------
__global__ __launch_bounds__(256, 2) void qkv_mm(
    const float* __restrict__ gq, const float* __restrict__ gk, const float* __restrict__ gv,
    const float* __restrict__ bq, const float* __restrict__ bk, const float* __restrict__ bv)
{
    extern __shared__ char dsm[];
    const int z = blockIdx.z;
    const int b = z & 31;
    const int m = z >> 5;
    const float* gate = (m == 0) ? gq : ((m == 1) ? gk : gv);
    const float* bias = (m == 0) ? bq : ((m == 1) ? bk : bv);
    __half* outp      = (m == 0) ? g_q : ((m == 1) ? g_k : g_v);

    const int m0 = blockIdx.y * 128;  // d
    const int n0 = blockIdx.x * 128;  // t
    const size_t base = (size_t)b * CT;

    float acc[2][8][4];
    mm_core<false>(g_w + (size_t)m * CC + (size_t)m0 * CDIM, CDIM,
                   g_x + base + n0, TDIM, CDIM, dsm, acc);

    const int lane = threadIdx.x & 31;
    const int wid  = threadIdx.x >> 5;
    const int wm = wid & 3, wn = wid >> 2;
#pragma unroll
    for (int mi = 0; mi < 2; mi++)
#pragma unroll
        for (int ni = 0; ni < 8; ni++) {
            int r = m0 + wm * 32 + mi * 16 + (lane >> 2);
            int c = n0 + wn * 64 + ni * 8 + (lane & 3) * 2;
#pragma unroll
            for (int h = 0; h < 2; h++) {
                int d = r + h * 8;
                float bi = bias[d];
                size_t off = base + (size_t)d * TDIM + c;
                float2 g = *reinterpret_cast<const float2*>(gate + off);
                *reinterpret_cast<__half2*>(outp + off) =
                    __floats2half2_rn((acc[mi][ni][h * 2 + 0] + bi) * g.x,
                                      (acc[mi][ni][h * 2 + 1] + bi) * g.y);
            }
        }
}

// ---------------------------------------------------------------------------
// 2) energy: E[c,d] = SCALE * sum_t q[c,t] k[d,t]   grid (4, 4, 32)
// ---------------------------------------------------------------------------
__global__ __launch_bounds__(256, 2) void energy_mm()
{
    extern __shared__ char dsm[];
    const int b  = blockIdx.z;
    const int m0 = blockIdx.y * 128;  // c
    const int n0 = blockIdx.x * 128;  // d
    const size_t base = (size_t)b * CT;

    float acc[2][8][4];
    mm_core<true>(g_q + base + (size_t)m0 * TDIM, TDIM,
                  g_k + base + (size_t)n0 * TDIM, TDIM, TDIM, dsm, acc);

    const int lane = threadIdx.x & 31;
    const int wid  = threadIdx.x >> 5;
    const int wm = wid & 3, wn = wid >> 2;
    const size_t ebase = (size_t)b * CC;
#pragma unroll
    for (int mi = 0; mi < 2; mi++)
#pragma unroll
        for (int ni = 0; ni < 8; ni++) {
            int r = m0 + wm * 32 + mi * 16 + (lane >> 2);
            int c = n0 + wn * 64 + ni * 8 + (lane & 3) * 2;
#pragma unroll
            for (int h = 0; h < 2; h++) {
                size_t off = ebase + (size_t)(r + h * 8) * CDIM + c;
                *reinterpret_cast<float2*>(g_e + off) =
                    make_float2(acc[mi][ni][h * 2 + 0] * SCALE_F,
                                acc[mi][ni][h * 2 + 1] * SCALE_F);
            }
        }
}

// ---------------------------------------------------------------------------
// 3) softmax over d (512) -> fp16 attn.  grid 16384 x 256
// ---------------------------------------------------------------------------
__global__ __launch_bounds__(256) void softmax_kernel()
{
    const size_t row = blockIdx.x;
    const float* e = g_e + row * CDIM;
    const int tid  = threadIdx.x;
    const int lane = tid & 31;
    const int warp = tid >> 5;

    __shared__ float wmax[8], wsum[8];

    float v0 = e[tid];
    float v1 = e[tid + 256];
    float m = fmaxf(v0, v1);
#pragma unroll
    for (int o = 16; o > 0; o >>= 1) m = fmaxf(m, __shfl_xor_sync(0xFFFFFFFFu, m, o));
    if (lane == 0) wmax[warp] = m;
    __syncthreads();
    float bm = wmax[0];
#pragma unroll
    for (int w = 1; w < 8; w++) bm = fmaxf(bm, wmax[w]);

    float e0 = __expf(v0 - bm);
    float e1 = __expf(v1 - bm);
    float s = e0 + e1;
#pragma unroll
    for (int o = 16; o > 0; o >>= 1) s += __shfl_xor_sync(0xFFFFFFFFu, s, o);
    if (lane == 0) wsum[warp] = s;
    __syncthreads();
    float bs = 0.0f;
#pragma unroll
    for (int w = 0; w < 8; w++) bs += wsum[w];

    const float inv = 1.0f / bs;
    g_a[row * CDIM + tid]       = __float2half(e0 * inv);
    g_a[row * CDIM + tid + 256] = __float2half(e1 * inv);
}

// ---------------------------------------------------------------------------
// 4) out[c,t] = sum_d attn[c,d] v[d,t]   grid (8, 4, 32)
// ---------------------------------------------------------------------------
__global__ __launch_bounds__(256, 2) void out_mm(float* __restrict__ out)
{
    extern __shared__ char dsm[];
    const int b  = blockIdx.z;
    const int m0 = blockIdx.y * 128;  // c
    const int n0 = blockIdx.x * 128;  // t
    const size_t base  = (size_t)b * CT;
    const size_t ebase = (size_t)b * CC;

    float acc[2][8][4];
    mm_core<false>(g_a + ebase + (size_t)m0 * CDIM, CDIM,
                   g_v + base + n0, TDIM, CDIM, dsm, acc);

    const int lane = threadIdx.x & 31;
    const int wid  = threadIdx.x >> 5;
    const int wm = wid & 3, wn = wid >> 2;
#pragma unroll
    for (int mi = 0; mi < 2; mi++)
#pragma unroll
        for (int ni = 0; ni < 8; ni++) {
            int r = m0 + wm * 32 + mi * 16 + (lane >> 2);
            int c = n0 + wn * 64 + ni * 8 + (lane & 3) * 2;
#pragma unroll
            for (int h = 0; h < 2; h++) {
                size_t off = base + (size_t)(r + h * 8) * TDIM + c;
                *reinterpret_cast<float2*>(out + off) =
                    make_float2(acc[mi][ni][h * 2 + 0], acc[mi][ni][h * 2 + 1]);
            }
        }
}

// ---------------------------------------------------------------------------
extern "C" void kernel_launch(void* const* d_in, const int* in_sizes, int n_in,
                              void* d_out, int out_size)
{
    const float* x  = (const float*)d_in[0];
    const float* gq = (const float*)d_in[1];
    const float* gk = (const float*)d_in[2];
    const float* gv = (const float*)d_in[3];
    const float* Wq = (const float*)d_in[4];
    const float* bq = (const float*)d_in[5];
    const float* Wk = (const float*)d_in[6];
    const float* bk = (const float*)d_in[7];
    const float* Wv = (const float*)d_in[8];
    const float* bv = (const float*)d_in[9];
    float* out = (float*)d_out;

    cudaFuncSetAttribute(qkv_mm,    cudaFuncAttributeMaxDynamicSharedMemorySize, SMEM_NN);
    cudaFuncSetAttribute(energy_mm, cudaFuncAttributeMaxDynamicSharedMemorySize, SMEM_NT);
    cudaFuncSetAttribute(out_mm,    cudaFuncAttributeMaxDynamicSharedMemorySize, SMEM_NN);

    wprep<<<dim3(CC / 2048, 3), 256>>>(Wq, Wk, Wv);
    xprep<<<(unsigned)(((size_t)BSZ * CT) / 2048), 256>>>(x);

    qkv_mm<<<dim3(TDIM / 128, CDIM / 128, 3 * BSZ), 256, SMEM_NN>>>(gq, gk, gv, bq, bk, bv);

    energy_mm<<<dim3(CDIM / 128, CDIM / 128, BSZ), 256, SMEM_NT>>>();

    softmax_kernel<<<BSZ * CDIM, 256>>>();

    out_mm<<<dim3(TDIM / 128, CDIM / 128, BSZ), 256, SMEM_NN>>>(out);
}

// round 13
// speedup vs baseline: 1.7698x; 1.0328x over previous
#include <cuda_runtime.h>
#include <cuda_fp16.h>
#include <cstdint>

#define BSZ 32
#define CDIM 512
#define TDIM 1024
#define SCALE_F 0.04419417382415922f  // 1/sqrt(512)
#define CT (CDIM * TDIM)
#define CC (CDIM * CDIM)

// ---------------------------------------------------------------------------
// Scratch (allocation-free rule: __device__ globals)
// ---------------------------------------------------------------------------
__device__ __align__(16) __half g_w[3 * CC];                 // fp16 W [m][d][c]
__device__ __align__(16) __half g_x[(size_t)BSZ * CT];       // fp16 x [b][c][t]
__device__ __align__(16) __half g_q[(size_t)BSZ * CT];       // fp16 q [b][c][t]
__device__ __align__(16) __half g_k[(size_t)BSZ * CT];       // fp16 k [b][d][t]
__device__ __align__(16) __half g_v[(size_t)BSZ * CT];       // fp16 v [b][d][t]
__device__ __align__(16) __half g_a[(size_t)BSZ * CC];       // fp16 attn [b][c][d]
__device__ __align__(16) float  g_e[(size_t)BSZ * CC];       // energy fp32 [b][c][d]

// SMEM strides (fp16 elems): A rows 80B apart (5 chunks mod 8),
// B-NN rows 272B apart (1 chunk mod 8) -> conflict-free ldmatrix (R2-proven).
#define ASTR 40
#define BSTR 136

// ---------------------------------------------------------------------------
// PTX wrappers
// ---------------------------------------------------------------------------
__device__ __forceinline__ void ldsm4(uint32_t& r0, uint32_t& r1, uint32_t& r2, uint32_t& r3,
                                      const void* p) {
    uint32_t a = (uint32_t)__cvta_generic_to_shared(p);
    asm volatile("ldmatrix.sync.aligned.m8n8.x4.shared.b16 {%0,%1,%2,%3},[%4];"
                 : "=r"(r0), "=r"(r1), "=r"(r2), "=r"(r3) : "r"(a));
}
__device__ __forceinline__ void ldsm4t(uint32_t& r0, uint32_t& r1, uint32_t& r2, uint32_t& r3,
                                       const void* p) {
    uint32_t a = (uint32_t)__cvta_generic_to_shared(p);
    asm volatile("ldmatrix.sync.aligned.m8n8.x4.trans.shared.b16 {%0,%1,%2,%3},[%4];"
                 : "=r"(r0), "=r"(r1), "=r"(r2), "=r"(r3) : "r"(a));
}
__device__ __forceinline__ void mma_f16(float* d, const uint32_t* a, const uint32_t* b) {
    asm volatile(
        "mma.sync.aligned.m16n8k16.row.col.f32.f16.f16.f32 "
        "{%0,%1,%2,%3},{%4,%5,%6,%7},{%8,%9},{%0,%1,%2,%3};"
        : "+f"(d[0]), "+f"(d[1]), "+f"(d[2]), "+f"(d[3])
        : "r"(a[0]), "r"(a[1]), "r"(a[2]), "r"(a[3]), "r"(b[0]), "r"(b[1]));
}

// ---------------------------------------------------------------------------
// Core: CTA tile 128x128, BK=32, 256 threads = 8 warps (4m x 2n), warp 32x64,
// fp16 single-pass. Register-pipelined synchronous staging, single smem buffer:
//   preload regs(0); { sync; STS(regs); sync; regs<-LDG(it+1); compute(it) }
// LDG(it+1) latency hides under compute(it); no cp.async, no wait_group.
// A [M,K] k-contig. BNT=false: B [K,N] n-contig. BNT=true: B [N,K] k-contig.
// ---------------------------------------------------------------------------
template <bool BNT>
__device__ __forceinline__ void mm_core(
    const __half* __restrict__ A, int lda,
    const __half* __restrict__ B, int ldb,
    int K, float acc[2][8][4])
{
    __shared__ __half As[128 * ASTR];
    __shared__ __half Bs[BNT ? (128 * ASTR) : (32 * BSTR)];

    const int tid  = threadIdx.x;
    const int lane = tid & 31;
    const int wid  = tid >> 5;
    const int wm   = wid & 3;    // m offset wm*32
    const int wn   = wid >> 2;   // n offset wn*64

#pragma unroll
    for (int mi = 0; mi < 2; mi++)
#pragma unroll
        for (int ni = 0; ni < 8; ni++)
#pragma unroll
            for (int r = 0; r < 4; r++) acc[mi][ni][r] = 0.0f;

    // staging addresses: each thread owns 16 contiguous elems per operand
    const int arow = tid >> 1;                 // 0..127
    const int ac0  = (tid & 1) * 16;           // 0 / 16
    const int bnrow = tid >> 3;                // 0..31   (NN path)
    const int bnc0  = (tid & 7) * 16;          // 0..112  (NN path)

    const __half* Ag = A + (size_t)arow * lda + ac0;
    const __half* Bg = BNT ? (B + (size_t)arow * ldb + ac0)
                           : (B + (size_t)bnrow * ldb + bnc0);

    uint4 ra0, ra1, rb0, rb1;
    // preload tile 0
    ra0 = *reinterpret_cast<const uint4*>(Ag);
    ra1 = *reinterpret_cast<const uint4*>(Ag + 8);
    rb0 = *reinterpret_cast<const uint4*>(Bg);
    rb1 = *reinterpret_cast<const uint4*>(Bg + 8);

    const int NT = K / 32;
    for (int it = 0; it < NT; ++it) {
        __syncthreads();   // previous compute done reading smem
        *reinterpret_cast<uint4*>(&As[arow * ASTR + ac0])     = ra0;
        *reinterpret_cast<uint4*>(&As[arow * ASTR + ac0 + 8]) = ra1;
        if (BNT) {
            *reinterpret_cast<uint4*>(&Bs[arow * ASTR + ac0])     = rb0;
            *reinterpret_cast<uint4*>(&Bs[arow * ASTR + ac0 + 8]) = rb1;
        } else {
            *reinterpret_cast<uint4*>(&Bs[bnrow * BSTR + bnc0])     = rb0;
            *reinterpret_cast<uint4*>(&Bs[bnrow * BSTR + bnc0 + 8]) = rb1;
        }
        __syncthreads();

        if (it + 1 < NT) {  // issue next tile's LDGs early; latency hides under MMAs
            const __half* An = Ag + (it + 1) * 32;
            ra0 = *reinterpret_cast<const uint4*>(An);
            ra1 = *reinterpret_cast<const uint4*>(An + 8);
            const __half* Bn = BNT ? (Bg + (it + 1) * 32)
                                   : (Bg + (size_t)(it + 1) * 32 * ldb);
            rb0 = *reinterpret_cast<const uint4*>(Bn);
            rb1 = *reinterpret_cast<const uint4*>(Bn + 8);
        }

#pragma unroll
        for (int ks = 0; ks < 2; ++ks) {
            uint32_t ah[2][4];
#pragma unroll
            for (int mi = 0; mi < 2; mi++) {
                int ar = wm * 32 + mi * 16 + (lane & 15);
                int ac = ks * 16 + (lane >> 4) * 8;
                ldsm4(ah[mi][0], ah[mi][1], ah[mi][2], ah[mi][3], &As[ar * ASTR + ac]);
            }
            uint32_t bh[4][4];
#pragma unroll
            for (int p = 0; p < 4; p++) {
                if (!BNT) {
                    int br = ks * 16 + (lane & 15);
                    int bc = wn * 64 + p * 16 + (lane >> 4) * 8;
                    ldsm4t(bh[p][0], bh[p][1], bh[p][2], bh[p][3], &Bs[br * BSTR + bc]);
                } else {
                    int q  = lane >> 3;
                    int nr = wn * 64 + p * 16 + (lane & 7) + ((q & 2) ? 8 : 0);
                    int kc = ks * 16 + ((q & 1) ? 8 : 0);
                    ldsm4(bh[p][0], bh[p][1], bh[p][2], bh[p][3], &Bs[nr * ASTR + kc]);
                }
            }
#pragma unroll
            for (int mi = 0; mi < 2; mi++)
#pragma unroll
                for (int p = 0; p < 4; p++)
#pragma unroll
                    for (int t = 0; t < 2; t++)
                        mma_f16(acc[mi][p * 2 + t], ah[mi], &bh[p][t * 2]);
        }
    }
}

// ---------------------------------------------------------------------------
// Prep kernels: fp16 casts
// ---------------------------------------------------------------------------
__global__ __launch_bounds__(256) void wprep(
    const float* __restrict__ Wq, const float* __restrict__ Wk, const float* __restrict__ Wv)
{
    const int m = blockIdx.y;
    const float* W = (m == 0) ? Wq : ((m == 1) ? Wk : Wv);
    size_t i = ((size_t)blockIdx.x * 256 + threadIdx.x) * 8;
    float4 a = *reinterpret_cast<const float4*>(W + i);
    float4 b = *reinterpret_cast<const float4*>(W + i + 4);
    union { __half h[8]; uint4 u; } o;
    o.h[0] = __float2half(a.x); o.h[1] = __float2half(a.y);
    o.h[2] = __float2half(a.z); o.h[3] = __float2half(a.w);
    o.h[4] = __float2half(b.x); o.h[5] = __float2half(b.y);
    o.h[6] = __float2half(b.z); o.h[7] = __float2half(b.w);
    *reinterpret_cast<uint4*>(&g_w[(size_t)m * CC + i]) = o.u;
}

__global__ __launch_bounds__(256) void xprep(const float* __restrict__ x)
{
    size_t i = ((size_t)blockIdx.x * 256 + threadIdx.x) * 8;
    float4 a = *reinterpret_cast<const float4*>(x + i);
    float4 b = *reinterpret_cast<const float4*>(x + i + 4);
    union { __half h[8]; uint4 u; } o;
    o.h[0] = __float2half(a.x); o.h[1] = __float2half(a.y);
    o.h[2] = __float2half(a.z); o.h[3] = __float2half(a.w);
    o.h[4] = __float2half(b.x); o.h[5] = __float2half(b.y);
    o.h[6] = __float2half(b.z); o.h[7] = __float2half(b.w);
    *reinterpret_cast<uint4*>(&g_x[i]) = o.u;
}

// ---------------------------------------------------------------------------
// 1) q/k/v projection: out[ch,t] = fp16(gate * (W @ x + bias))
//    grid (8, 4, 96), z = m*32 + b
// ---------------------------------------------------------------------------
__global__ __launch_bounds__(256) void qkv_mm(
    const float* __restrict__ gq, const float* __restrict__ gk, const float* __restrict__ gv,
    const float* __restrict__ bq, const float* __restrict__ bk, const float* __restrict__ bv)
{
    const int z = blockIdx.z;
    const int b = z & 31;
    const int m = z >> 5;
    const float* gate = (m == 0) ? gq : ((m == 1) ? gk : gv);
    const float* bias = (m == 0) ? bq : ((m == 1) ? bk : bv);
    __half* outp      = (m == 0) ? g_q : ((m == 1) ? g_k : g_v);

    const int m0 = blockIdx.y * 128;  // d
    const int n0 = blockIdx.x * 128;  // t
    const size_t base = (size_t)b * CT;

    float acc[2][8][4];
    mm_core<false>(g_w + (size_t)m * CC + (size_t)m0 * CDIM, CDIM,
                   g_x + base + n0, TDIM, CDIM, acc);

    const int lane = threadIdx.x & 31;
    const int wid  = threadIdx.x >> 5;
    const int wm = wid & 3, wn = wid >> 2;
#pragma unroll
    for (int mi = 0; mi < 2; mi++)
#pragma unroll
        for (int ni = 0; ni < 8; ni++) {
            int r = m0 + wm * 32 + mi * 16 + (lane >> 2);
            int c = n0 + wn * 64 + ni * 8 + (lane & 3) * 2;
#pragma unroll
            for (int h = 0; h < 2; h++) {
                int d = r + h * 8;
                float bi = bias[d];
                size_t off = base + (size_t)d * TDIM + c;
                float2 g = *reinterpret_cast<const float2*>(gate + off);
                *reinterpret_cast<__half2*>(outp + off) =
                    __floats2half2_rn((acc[mi][ni][h * 2 + 0] + bi) * g.x,
                                      (acc[mi][ni][h * 2 + 1] + bi) * g.y);
            }
        }
}

// ---------------------------------------------------------------------------
// 2) energy: E[c,d] = SCALE * sum_t q[c,t] k[d,t]   grid (4, 4, 32)
// ---------------------------------------------------------------------------
__global__ __launch_bounds__(256) void energy_mm()
{
    const int b  = blockIdx.z;
    const int m0 = blockIdx.y * 128;  // c
    const int n0 = blockIdx.x * 128;  // d
    const size_t base = (size_t)b * CT;

    float acc[2][8][4];
    mm_core<true>(g_q + base + (size_t)m0 * TDIM, TDIM,
                  g_k + base + (size_t)n0 * TDIM, TDIM, TDIM, acc);

    const int lane = threadIdx.x & 31;
    const int wid  = threadIdx.x >> 5;
    const int wm = wid & 3, wn = wid >> 2;
    const size_t ebase = (size_t)b * CC;
#pragma unroll
    for (int mi = 0; mi < 2; mi++)
#pragma unroll
        for (int ni = 0; ni < 8; ni++) {
            int r = m0 + wm * 32 + mi * 16 + (lane >> 2);
            int c = n0 + wn * 64 + ni * 8 + (lane & 3) * 2;
#pragma unroll
            for (int h = 0; h < 2; h++) {
                size_t off = ebase + (size_t)(r + h * 8) * CDIM + c;
                *reinterpret_cast<float2*>(g_e + off) =
                    make_float2(acc[mi][ni][h * 2 + 0] * SCALE_F,
                                acc[mi][ni][h * 2 + 1] * SCALE_F);
            }
        }
}

// ---------------------------------------------------------------------------
// 3) softmax over d (512) -> fp16 attn.  grid 16384 x 256
// ---------------------------------------------------------------------------
__global__ __launch_bounds__(256) void softmax_kernel()
{
    const size_t row = blockIdx.x;
    const float* e = g_e + row * CDIM;
    const int tid  = threadIdx.x;
    const int lane = tid & 31;
    const int warp = tid >> 5;

    __shared__ float wmax[8], wsum[8];

    float v0 = e[tid];
    float v1 = e[tid + 256];
    float m = fmaxf(v0, v1);
#pragma unroll
    for (int o = 16; o > 0; o >>= 1) m = fmaxf(m, __shfl_xor_sync(0xFFFFFFFFu, m, o));
    if (lane == 0) wmax[warp] = m;
    __syncthreads();
    float bm = wmax[0];
#pragma unroll
    for (int w = 1; w < 8; w++) bm = fmaxf(bm, wmax[w]);

    float e0 = __expf(v0 - bm);
    float e1 = __expf(v1 - bm);
    float s = e0 + e1;
#pragma unroll
    for (int o = 16; o > 0; o >>= 1) s += __shfl_xor_sync(0xFFFFFFFFu, s, o);
    if (lane == 0) wsum[warp] = s;
    __syncthreads();
    float bs = 0.0f;
#pragma unroll
    for (int w = 0; w < 8; w++) bs += wsum[w];

    const float inv = 1.0f / bs;
    g_a[row * CDIM + tid]       = __float2half(e0 * inv);
    g_a[row * CDIM + tid + 256] = __float2half(e1 * inv);
}

// ---------------------------------------------------------------------------
// 4) out[c,t] = sum_d attn[c,d] v[d,t]   grid (8, 4, 32)
// ---------------------------------------------------------------------------
__global__ __launch_bounds__(256) void out_mm(float* __restrict__ out)
{
    const int b  = blockIdx.z;
    const int m0 = blockIdx.y * 128;  // c
    const int n0 = blockIdx.x * 128;  // t
    const size_t base  = (size_t)b * CT;
    const size_t ebase = (size_t)b * CC;

    float acc[2][8][4];
    mm_core<false>(g_a + ebase + (size_t)m0 * CDIM, CDIM,
                   g_v + base + n0, TDIM, CDIM, acc);

    const int lane = threadIdx.x & 31;
    const int wid  = threadIdx.x >> 5;
    const int wm = wid & 3, wn = wid >> 2;
#pragma unroll
    for (int mi = 0; mi < 2; mi++)
#pragma unroll
        for (int ni = 0; ni < 8; ni++) {
            int r = m0 + wm * 32 + mi * 16 + (lane >> 2);
            int c = n0 + wn * 64 + ni * 8 + (lane & 3) * 2;
#pragma unroll
            for (int h = 0; h < 2; h++) {
                size_t off = base + (size_t)(r + h * 8) * TDIM + c;
                *reinterpret_cast<float2*>(out + off) =
                    make_float2(acc[mi][ni][h * 2 + 0], acc[mi][ni][h * 2 + 1]);
            }
        }
}

// ---------------------------------------------------------------------------
extern "C" void kernel_launch(void* const* d_in, const int* in_sizes, int n_in,
                              void* d_out, int out_size)
{
    const float* x  = (const float*)d_in[0];
    const float* gq = (const float*)d_in[1];
    const float* gk = (const float*)d_in[2];
    const float* gv = (const float*)d_in[3];
    const float* Wq = (const float*)d_in[4];
    const float* bq = (const float*)d_in[5];
    const float* Wk = (const float*)d_in[6];
    const float* bk = (const float*)d_in[7];
    const float* Wv = (const float*)d_in[8];
    const float* bv = (const float*)d_in[9];
    float* out = (float*)d_out;

    wprep<<<dim3(CC / 2048, 3), 256>>>(Wq, Wk, Wv);
    xprep<<<(unsigned)(((size_t)BSZ * CT) / 2048), 256>>>(x);

    qkv_mm<<<dim3(TDIM / 128, CDIM / 128, 3 * BSZ), 256>>>(gq, gk, gv, bq, bk, bv);

    energy_mm<<<dim3(CDIM / 128, CDIM / 128, BSZ), 256>>>();

    softmax_kernel<<<BSZ * CDIM, 256>>>();

    out_mm<<<dim3(TDIM / 128, CDIM / 128, BSZ), 256>>>(out);
}